// round 1
// baseline (speedup 1.0000x reference)
#include <cuda_runtime.h>

// ---------------------------------------------------------------------------
// RNN_28260884808397 on GB300 (sm_103a)
//
// Decomposition:
//   pass1: g_xp = input @ W1x^T + b1          (dense, parallel)
//   pass2: h_t  = relu(h_{t-1} @ W1h^T + xp_t) sequential scan, one CTA per
//          batch element; W1h row per-thread in registers, h in shared,
//          packed fp32x2 FMA (fma.rn.f32x2) for 2x fp32 throughput.
//          h_t streamed to g_h.
//   pass3: out  = relu(g_h @ W2^T + b2)       (dense, parallel)
// ---------------------------------------------------------------------------

#define B_DIM 64
#define T_DIM 4096
#define NH 128
#define NTOKENS (B_DIM * T_DIM)

// Scratch (device globals: no runtime allocation allowed)
__device__ float g_xp[(size_t)NTOKENS * NH];
__device__ float g_h [(size_t)NTOKENS * NH];

typedef unsigned long long u64;

// packed 2-wide fp32 FMA: d = a*b + c (elementwise on packed pairs)
__device__ __forceinline__ u64 ffma2(u64 a, u64 b, u64 c) {
    u64 d;
    asm("fma.rn.f32x2 %0, %1, %2, %3;" : "=l"(d) : "l"(a), "l"(b), "l"(c));
    return d;
}

__device__ __forceinline__ float hsum2(u64 a) {
    unsigned lo, hi;
    asm("mov.b64 {%0, %1}, %2;" : "=r"(lo), "=r"(hi) : "l"(a));
    return __uint_as_float(lo) + __uint_as_float(hi);
}

// 128-long dot product: w = 64 packed pairs (registers), vec = 128 floats
// (shared, 16B aligned). 4 independent accumulator chains.
__device__ __forceinline__ float dot128(const u64* __restrict__ w,
                                        const float* vec) {
    const ulonglong2* hp = reinterpret_cast<const ulonglong2*>(vec);
    u64 a0 = 0ull, a1 = 0ull, a2 = 0ull, a3 = 0ull;
#pragma unroll
    for (int i = 0; i < 16; i++) {
        ulonglong2 h0 = hp[2 * i];
        ulonglong2 h1 = hp[2 * i + 1];
        a0 = ffma2(w[4 * i + 0], h0.x, a0);
        a1 = ffma2(w[4 * i + 1], h0.y, a1);
        a2 = ffma2(w[4 * i + 2], h1.x, a2);
        a3 = ffma2(w[4 * i + 3], h1.y, a3);
    }
    return (hsum2(a0) + hsum2(a1)) + (hsum2(a2) + hsum2(a3));
}

// Load one 128-float weight row (16B aligned) into 64 packed registers.
__device__ __forceinline__ void load_wrow(u64* w, const float* base) {
    const ulonglong2* wp = reinterpret_cast<const ulonglong2*>(base);
#pragma unroll
    for (int i = 0; i < 32; i++) {
        ulonglong2 v = wp[i];
        w[2 * i]     = v.x;
        w[2 * i + 1] = v.y;
    }
}

// ---------------------------------------------------------------------------
// Dense GEMM body: C[tok][j] = act( A[tok][:] . wrow_j[:] + bias[j] )
// 128 threads; thread j owns output column j (weight row in registers).
// Each CTA processes 64 tokens staged through shared memory.
// ---------------------------------------------------------------------------
template <bool RELU>
__device__ __forceinline__ void gemm_body(const float* __restrict__ A,
                                          const float* __restrict__ wrow_base,
                                          const float* __restrict__ bias,
                                          float* __restrict__ C) {
    __shared__ __align__(16) float tile[64 * NH];
    const int j = threadIdx.x;

    u64 w[64];
    load_wrow(w, wrow_base);
    const float bj = bias[j];

    const size_t base = (size_t)blockIdx.x * 64 * NH;

    // Stage 64 token rows (coalesced; 64 independent LDGs -> deep MLP)
#pragma unroll
    for (int k = 0; k < 64; k++) {
        tile[k * NH + j] = A[base + (size_t)k * NH + j];
    }
    __syncthreads();

#pragma unroll 4
    for (int m = 0; m < 64; m++) {
        float s = dot128(w, &tile[m * NH]) + bj;
        if (RELU) s = fmaxf(s, 0.0f);
        C[base + (size_t)m * NH + j] = s;
    }
}

__global__ void __launch_bounds__(128)
k_xproj(const float* __restrict__ in, const float* __restrict__ W1,
        const float* __restrict__ b1) {
    // W1 is (128, 256) row-major; W1x row j = W1[j, 128:256]
    gemm_body<false>(in, W1 + (size_t)threadIdx.x * 256 + 128, b1, g_xp);
}

__global__ void __launch_bounds__(128)
k_out(const float* __restrict__ W2, const float* __restrict__ b2,
      float* __restrict__ out) {
    // W2 is (128, 128) row-major
    gemm_body<true>(g_h, W2 + (size_t)threadIdx.x * NH, b2, out);
}

// ---------------------------------------------------------------------------
// Sequential scan: one CTA per batch element. 128 threads; thread j owns
// hidden unit j. W1h row in registers; h double-buffered in shared; one
// barrier per step. xp prefetched 8 steps ahead in a register queue.
// ---------------------------------------------------------------------------
__global__ void __launch_bounds__(128)
k_scan(const float* __restrict__ W1) {
    const int j = threadIdx.x;
    const int b = blockIdx.x;

    u64 w[64];
    // W1h row j = W1[j, 0:128]
    load_wrow(w, W1 + (size_t)j * 256);

    __shared__ __align__(16) float hbuf[2][NH];
    hbuf[0][j] = 0.0f;

    const float* __restrict__ xp = g_xp + (size_t)b * T_DIM * NH + j;
    float* __restrict__ Hb       = g_h  + (size_t)b * T_DIM * NH + j;

    // 8-deep prefetch queue (indices resolved by unroll-8 below)
    float q[8];
#pragma unroll
    for (int k = 0; k < 8; k++) q[k] = xp[(size_t)k * NH];

    __syncthreads();

#pragma unroll 8
    for (int t = 0; t < T_DIM; t++) {
        float s = dot128(w, hbuf[t & 1]);

        float x = q[t & 7];
        const int tp = t + 8;
        if (tp < T_DIM) q[t & 7] = xp[(size_t)tp * NH];

        float hn = fmaxf(s + x, 0.0f);

        Hb[(size_t)t * NH] = hn;      // stream h_t out for pass3
        hbuf[(t + 1) & 1][j] = hn;    // publish for next step
        __syncthreads();
    }
}

// ---------------------------------------------------------------------------
// Launch
// inputs (metadata order): input f32[64,4096,128], W1 f32[128,256],
//                          b1 f32[128], W2 f32[128,128], b2 f32[128]
// output: f32[64,4096,128]
// ---------------------------------------------------------------------------
extern "C" void kernel_launch(void* const* d_in, const int* in_sizes, int n_in,
                              void* d_out, int out_size) {
    const float* in = (const float*)d_in[0];
    const float* W1 = (const float*)d_in[1];
    const float* b1 = (const float*)d_in[2];
    const float* W2 = (const float*)d_in[3];
    const float* b2 = (const float*)d_in[4];
    float* out = (float*)d_out;

    const int gemm_blocks = NTOKENS / 64;  // 4096

    k_xproj<<<gemm_blocks, 128>>>(in, W1, b1);
    k_scan<<<B_DIM, 128>>>(W1);
    k_out<<<gemm_blocks, 128>>>(W2, b2, out);
}

// round 3
// speedup vs baseline: 1.1506x; 1.1506x over previous
#include <cuda_runtime.h>

// ---------------------------------------------------------------------------
// RNN_28260884808397 on GB300 (sm_103a) — Round 3 (Round 2 + dot64 fix)
//
// K-split-by-2 layout everywhere:
//   256 threads; warp w owns outputs [w*16, w*16+16); lanes 0-15 compute the
//   K[0:64) partial dot, lanes 16-31 compute K[64:128); one shfl.xor(16)
//   combines. Per-thread weight storage = 32 u64 (64 regs).
// Round 2 bug: dot64 consumed only 32 of 64 K elements (loop i<4 -> i<8).
// ---------------------------------------------------------------------------

#define B_DIM 64
#define T_DIM 4096
#define NH 128
#define NTOKENS (B_DIM * T_DIM)

__device__ float g_xp[(size_t)NTOKENS * NH];
__device__ float g_h [(size_t)NTOKENS * NH];

typedef unsigned long long u64;

__device__ __forceinline__ u64 ffma2(u64 a, u64 b, u64 c) {
    u64 d;
    asm("fma.rn.f32x2 %0, %1, %2, %3;" : "=l"(d) : "l"(a), "l"(b), "l"(c));
    return d;
}

__device__ __forceinline__ float hsum2(u64 a) {
    unsigned lo, hi;
    asm("mov.b64 {%0, %1}, %2;" : "=r"(lo), "=r"(hi) : "l"(a));
    return __uint_as_float(lo) + __uint_as_float(hi);
}

// 64-long partial dot: w = 32 packed pairs (regs), vec = 64 floats in shared
// (16B aligned). 4 independent chains of depth 8. Consumes all 32 w regs.
__device__ __forceinline__ float dot64(const u64* __restrict__ w,
                                       const float* vec) {
    const ulonglong2* hp = reinterpret_cast<const ulonglong2*>(vec);
    u64 a0 = 0ull, a1 = 0ull, a2 = 0ull, a3 = 0ull;
#pragma unroll
    for (int i = 0; i < 8; i++) {              // FIX: was i < 4
        ulonglong2 h0 = hp[2 * i];
        ulonglong2 h1 = hp[2 * i + 1];
        a0 = ffma2(w[4 * i + 0], h0.x, a0);
        a1 = ffma2(w[4 * i + 1], h0.y, a1);
        a2 = ffma2(w[4 * i + 2], h1.x, a2);
        a3 = ffma2(w[4 * i + 3], h1.y, a3);
    }
    return (hsum2(a0) + hsum2(a1)) + (hsum2(a2) + hsum2(a3));
}

// Load 64 floats (one K-half of a weight row) into 32 packed registers.
__device__ __forceinline__ void load_wrow32(u64* w, const float* base) {
    const ulonglong2* wp = reinterpret_cast<const ulonglong2*>(base);
#pragma unroll
    for (int i = 0; i < 16; i++) {
        ulonglong2 v = wp[i];
        w[2 * i]     = v.x;
        w[2 * i + 1] = v.y;
    }
}

// ---------------------------------------------------------------------------
// Dense GEMM: C[tok][out] = act( A[tok][:] . wrow_out[:] + bias[out] )
// 256 threads, K-split pairs via lane groups, 64 tokens staged per CTA.
// ---------------------------------------------------------------------------
template <bool RELU>
__device__ __forceinline__ void gemm_body(const float* __restrict__ A,
                                          const float* __restrict__ W,
                                          int wstride, int woff,
                                          const float* __restrict__ bias,
                                          float* __restrict__ C) {
    __shared__ __align__(16) float tile[64 * NH];
    const int tid   = threadIdx.x;
    const int wid   = tid >> 5;          // 0..7
    const int lane  = tid & 31;
    const int half  = lane >> 4;         // 0 or 1 (K half)
    const int out   = wid * 16 + (lane & 15);

    u64 w[32];
    load_wrow32(w, W + (size_t)out * wstride + woff + half * 64);
    const float bj = bias[out];

    const size_t base = (size_t)blockIdx.x * 64 * NH;

    // Stage 64 token rows, coalesced float4 loads
    {
        const float4* A4 = reinterpret_cast<const float4*>(A + base);
        float4* T4 = reinterpret_cast<float4*>(tile);
#pragma unroll
        for (int i = 0; i < 8; i++)
            T4[i * 256 + tid] = A4[i * 256 + tid];
    }
    __syncthreads();

#pragma unroll 4
    for (int m = 0; m < 64; m++) {
        float p = dot64(w, &tile[m * NH + half * 64]);
        float s = p + __shfl_xor_sync(0xffffffffu, p, 16);
        if (half == 0) {
            s += bj;
            if (RELU) s = fmaxf(s, 0.0f);
            C[base + (size_t)m * NH + out] = s;
        }
    }
}

__global__ void __launch_bounds__(256)
k_xproj(const float* __restrict__ in, const float* __restrict__ W1,
        const float* __restrict__ b1) {
    // W1 is (128, 256) row-major; W1x = W1[:, 128:256]
    gemm_body<false>(in, W1, 256, 128, b1, g_xp);
}

__global__ void __launch_bounds__(256)
k_out(const float* __restrict__ W2, const float* __restrict__ b2,
      float* __restrict__ out) {
    gemm_body<true>(g_h, W2, 128, 0, b2, out);
}

// ---------------------------------------------------------------------------
// Sequential scan: one CTA (256 threads, 8 warps) per batch element.
// Thread pair (lane, lane+16) owns output `out`; each computes one K-half.
// h double-buffered in shared; one barrier per step; xp prefetched 8 ahead.
// ---------------------------------------------------------------------------
__global__ void __launch_bounds__(256)
k_scan(const float* __restrict__ W1) {
    const int tid  = threadIdx.x;
    const int wid  = tid >> 5;
    const int lane = tid & 31;
    const int half = lane >> 4;
    const int out  = wid * 16 + (lane & 15);
    const int b    = blockIdx.x;

    u64 w[32];
    // W1h row `out` = W1[out, 0:128]; this thread takes K-half `half`
    load_wrow32(w, W1 + (size_t)out * 256 + half * 64);

    __shared__ __align__(16) float hbuf[2][NH];
    if (half == 0) hbuf[0][out] = 0.0f;

    const float* __restrict__ xp = g_xp + (size_t)b * T_DIM * NH + out;
    float* __restrict__ Hb       = g_h  + (size_t)b * T_DIM * NH + out;

    float q[8];
#pragma unroll
    for (int k = 0; k < 8; k++) q[k] = xp[(size_t)k * NH];

    __syncthreads();

#pragma unroll 8
    for (int t = 0; t < T_DIM; t++) {
        const int cur = t & 1;
        float p = dot64(w, &hbuf[cur][half * 64]);
        float s = p + __shfl_xor_sync(0xffffffffu, p, 16);

        float x = q[t & 7];
        const int tp = t + 8;
        if (tp < T_DIM) q[t & 7] = xp[(size_t)tp * NH];

        float hn = fmaxf(s + x, 0.0f);

        if (half == 0) {
            Hb[(size_t)t * NH] = hn;       // stream h_t for pass3
            hbuf[cur ^ 1][out] = hn;       // publish for next step
        }
        __syncthreads();
    }
}

// ---------------------------------------------------------------------------
// Launch
// inputs: input f32[64,4096,128], W1 f32[128,256], b1 f32[128],
//         W2 f32[128,128], b2 f32[128];  output f32[64,4096,128]
// ---------------------------------------------------------------------------
extern "C" void kernel_launch(void* const* d_in, const int* in_sizes, int n_in,
                              void* d_out, int out_size) {
    const float* in = (const float*)d_in[0];
    const float* W1 = (const float*)d_in[1];
    const float* b1 = (const float*)d_in[2];
    const float* W2 = (const float*)d_in[3];
    const float* b2 = (const float*)d_in[4];
    float* out = (float*)d_out;

    const int gemm_blocks = NTOKENS / 64;  // 4096

    k_xproj<<<gemm_blocks, 256>>>(in, W1, b1);
    k_scan<<<B_DIM, 256>>>(W1);
    k_out<<<gemm_blocks, 256>>>(W2, b2, out);
}

// round 4
// speedup vs baseline: 1.2762x; 1.1091x over previous
#include <cuda_runtime.h>

// ---------------------------------------------------------------------------
// RNN_28260884808397 on GB300 (sm_103a) — Round 4
//
//   pass1: g_xp = input @ W1x^T + b1      (k_xproj, unchanged from R3)
//   pass2: fused scan+output (k_scan_out):
//          at step t (reading h_{t-1} from smem ONCE):
//             h_t      = relu(W1h . h_{t-1} + xp_t)
//             out_{t-1}= relu(W2  . h_{t-1} + b2)     -> written to d_out
//          W1h and W2 rows both live in registers (1 CTA/SM, pressure free).
//          Branch-free inner loop; k_out kernel and g_h scratch eliminated.
// ---------------------------------------------------------------------------

#define B_DIM 64
#define T_DIM 4096
#define NH 128
#define NTOKENS (B_DIM * T_DIM)

__device__ float g_xp[(size_t)NTOKENS * NH];

typedef unsigned long long u64;

__device__ __forceinline__ u64 ffma2(u64 a, u64 b, u64 c) {
    u64 d;
    asm("fma.rn.f32x2 %0, %1, %2, %3;" : "=l"(d) : "l"(a), "l"(b), "l"(c));
    return d;
}

__device__ __forceinline__ u64 addx2(u64 a, u64 b) {
    u64 d;
    asm("add.rn.f32x2 %0, %1, %2;" : "=l"(d) : "l"(a), "l"(b));
    return d;
}

__device__ __forceinline__ float hsum2(u64 a) {
    unsigned lo, hi;
    asm("mov.b64 {%0, %1}, %2;" : "=r"(lo), "=r"(hi) : "l"(a));
    return __uint_as_float(lo) + __uint_as_float(hi);
}

// 64-long partial dot, single weight set (used by GEMM + epilogue).
__device__ __forceinline__ float dot64(const u64* __restrict__ w,
                                       const float* vec) {
    const ulonglong2* hp = reinterpret_cast<const ulonglong2*>(vec);
    u64 a0 = 0ull, a1 = 0ull, a2 = 0ull, a3 = 0ull;
#pragma unroll
    for (int i = 0; i < 8; i++) {
        ulonglong2 h0 = hp[2 * i];
        ulonglong2 h1 = hp[2 * i + 1];
        a0 = ffma2(w[4 * i + 0], h0.x, a0);
        a1 = ffma2(w[4 * i + 1], h0.y, a1);
        a2 = ffma2(w[4 * i + 2], h1.x, a2);
        a3 = ffma2(w[4 * i + 3], h1.y, a3);
    }
    return hsum2(addx2(addx2(a0, a1), addx2(a2, a3)));
}

// Dual 64-long partial dot sharing one LDS pass: 8 independent ffma2 chains.
__device__ __forceinline__ void dual_dot64(const u64* __restrict__ wa,
                                           const u64* __restrict__ wb,
                                           const float* vec,
                                           float& ra, float& rb) {
    const ulonglong2* hp = reinterpret_cast<const ulonglong2*>(vec);
    u64 a0 = 0ull, a1 = 0ull, a2 = 0ull, a3 = 0ull;
    u64 b0 = 0ull, b1 = 0ull, b2 = 0ull, b3 = 0ull;
#pragma unroll
    for (int i = 0; i < 8; i++) {
        ulonglong2 h0 = hp[2 * i];
        ulonglong2 h1 = hp[2 * i + 1];
        a0 = ffma2(wa[4 * i + 0], h0.x, a0);
        b0 = ffma2(wb[4 * i + 0], h0.x, b0);
        a1 = ffma2(wa[4 * i + 1], h0.y, a1);
        b1 = ffma2(wb[4 * i + 1], h0.y, b1);
        a2 = ffma2(wa[4 * i + 2], h1.x, a2);
        b2 = ffma2(wb[4 * i + 2], h1.x, b2);
        a3 = ffma2(wa[4 * i + 3], h1.y, a3);
        b3 = ffma2(wb[4 * i + 3], h1.y, b3);
    }
    ra = hsum2(addx2(addx2(a0, a1), addx2(a2, a3)));
    rb = hsum2(addx2(addx2(b0, b1), addx2(b2, b3)));
}

// Load 64 floats (one K-half of a weight row) into 32 packed registers.
__device__ __forceinline__ void load_wrow32(u64* w, const float* base) {
    const ulonglong2* wp = reinterpret_cast<const ulonglong2*>(base);
#pragma unroll
    for (int i = 0; i < 16; i++) {
        ulonglong2 v = wp[i];
        w[2 * i]     = v.x;
        w[2 * i + 1] = v.y;
    }
}

// ---------------------------------------------------------------------------
// k_xproj: g_xp = input @ W1x^T + b1 (unchanged from R3)
// ---------------------------------------------------------------------------
__global__ void __launch_bounds__(256)
k_xproj(const float* __restrict__ in, const float* __restrict__ W1,
        const float* __restrict__ b1) {
    __shared__ __align__(16) float tile[64 * NH];
    const int tid   = threadIdx.x;
    const int wid   = tid >> 5;
    const int lane  = tid & 31;
    const int half  = lane >> 4;
    const int out   = wid * 16 + (lane & 15);

    u64 w[32];
    load_wrow32(w, W1 + (size_t)out * 256 + 128 + half * 64);
    const float bj = b1[out];

    const size_t base = (size_t)blockIdx.x * 64 * NH;

    {
        const float4* A4 = reinterpret_cast<const float4*>(in + base);
        float4* T4 = reinterpret_cast<float4*>(tile);
#pragma unroll
        for (int i = 0; i < 8; i++)
            T4[i * 256 + tid] = A4[i * 256 + tid];
    }
    __syncthreads();

#pragma unroll 4
    for (int m = 0; m < 64; m++) {
        float p = dot64(w, &tile[m * NH + half * 64]);
        float s = p + __shfl_xor_sync(0xffffffffu, p, 16);
        if (half == 0) {
            g_xp[base + (size_t)m * NH + out] = s + bj;
        }
    }
}

// ---------------------------------------------------------------------------
// k_scan_out: fused recurrence + output projection.
// One CTA (256 threads / 8 warps) per sequence. Thread pair (lane, lane^16)
// owns output `o`; lane group gives K-half. Per step, ONE shared LDS pass of
// h_{t-1} feeds both the W1h dot (-> h_t) and the W2 dot (-> out_{t-1}).
// ---------------------------------------------------------------------------
__global__ void __launch_bounds__(256)
k_scan_out(const float* __restrict__ W1, const float* __restrict__ W2,
           const float* __restrict__ b2, float* __restrict__ out) {
    const int tid  = threadIdx.x;
    const int wid  = tid >> 5;
    const int lane = tid & 31;
    const int half = lane >> 4;
    const int o    = wid * 16 + (lane & 15);
    const int b    = blockIdx.x;

    u64 w1[32], w2[32];
    load_wrow32(w1, W1 + (size_t)o * 256 + half * 64);   // W1h row o, K-half
    load_wrow32(w2, W2 + (size_t)o * NH  + half * 64);   // W2  row o, K-half
    const float bias2 = b2[o];

    __shared__ __align__(16) float hbuf[2][NH];
    hbuf[0][o] = 0.0f;   // both halves write the same value: benign

    const float* __restrict__ xp = g_xp + (size_t)b * T_DIM * NH + o;
    float* __restrict__ ob       = out  + (size_t)b * T_DIM * NH + o;

    float q[8];
#pragma unroll
    for (int k = 0; k < 8; k++) q[k] = xp[(size_t)k * NH];

    __syncthreads();

#pragma unroll 8
    for (int t = 0; t < T_DIM; t++) {
        const int cur = t & 1;

        float sh, so;
        dual_dot64(w1, w2, &hbuf[cur][half * 64], sh, so);
        sh += __shfl_xor_sync(0xffffffffu, sh, 16);
        so += __shfl_xor_sync(0xffffffffu, so, 16);

        // h_t = relu(W1h.h_{t-1} + xp_t)
        float hn = fmaxf(sh + q[t & 7], 0.0f);

        // branch-free prefetch (clamped index; redundant tail loads benign)
        int tp = t + 8; tp = (tp < T_DIM) ? tp : (T_DIM - 1);
        q[t & 7] = xp[(size_t)tp * NH];

        // out_{t-1} = relu(W2.h_{t-1} + b2); t=0 writes deterministic junk
        // (relu(b2)) to slot 0, overwritten by the t=1 iteration.
        int ts = t - 1; ts = (ts > 0) ? ts : 0;
        ob[(size_t)ts * NH] = fmaxf(so + bias2, 0.0f);

        hbuf[cur ^ 1][o] = hn;   // both halves write the same value: benign
        __syncthreads();
    }

    // epilogue: out_{T-1} from h_{T-1} (in hbuf[T_DIM & 1])
    {
        float p = dot64(w2, &hbuf[T_DIM & 1][half * 64]);
        float s = p + __shfl_xor_sync(0xffffffffu, p, 16);
        ob[(size_t)(T_DIM - 1) * NH] = fmaxf(s + bias2, 0.0f);
    }
}

// ---------------------------------------------------------------------------
// Launch
// inputs: input f32[64,4096,128], W1 f32[128,256], b1 f32[128],
//         W2 f32[128,128], b2 f32[128];  output f32[64,4096,128]
// ---------------------------------------------------------------------------
extern "C" void kernel_launch(void* const* d_in, const int* in_sizes, int n_in,
                              void* d_out, int out_size) {
    const float* in = (const float*)d_in[0];
    const float* W1 = (const float*)d_in[1];
    const float* b1 = (const float*)d_in[2];
    const float* W2 = (const float*)d_in[3];
    const float* b2 = (const float*)d_in[4];
    float* out = (float*)d_out;

    k_xproj<<<NTOKENS / 64, 256>>>(in, W1, b1);
    k_scan_out<<<B_DIM, 256>>>(W1, W2, b2, out);
}